// round 6
// baseline (speedup 1.0000x reference)
#include <cuda_runtime.h>
#include <cuda_fp16.h>
#include <math_constants.h>

#define NN 50000
#define NE 800000
#define FIN 128
#define DD 64
#define HH 4
#define HD 256   // H*D
#define EDIM 20

#define SCHUNK 200
#define NSB 250   // NSB * SCHUNK == NN

// ---------------- scratch (device globals) ----------------
__device__ float  g_h[NN * DD];          // 12.8 MB node features
__device__ __half g_xl[NN * HD];         // 25.6 MB (fp16 gather payload)
__device__ float  g_xr[NN * HD];         // 51.2 MB
__device__ __half g_eecsr[NE * HD];      // 410 MB ee = e@We (CSR order, fp16)
__device__ int    g_cnt[NN];
__device__ int    g_cur[NN];
__device__ int    g_rowptr[NN + 1];
__device__ int    g_bsum[NSB];
__device__ int    g_csr_src[NE];
__device__ int    g_csr_eid[NE];

// ---------------- h0 = relu(x @ f_W + f_b) ----------------
__global__ void k_h0(const float* __restrict__ x, const float* __restrict__ fW,
                     const float* __restrict__ fb) {
    __shared__ float Ws[FIN * DD];
    __shared__ float xs[4][FIN];
    int t = threadIdx.x;
    for (int i = t; i < FIN * DD; i += 256) Ws[i] = fW[i];
    int n0 = blockIdx.x * 4;
    for (int i = t; i < 4 * FIN; i += 256) {
        int r = i / FIN, k = i % FIN;
        int n = n0 + r;
        xs[r][k] = (n < NN) ? x[n * FIN + k] : 0.f;
    }
    __syncthreads();
    int r = t >> 6, d = t & 63;
    int n = n0 + r;
    if (n < NN) {
        float acc = fb[d];
#pragma unroll 8
        for (int k = 0; k < FIN; k++) acc = fmaf(xs[r][k], Ws[k * DD + d], acc);
        g_h[n * DD + d] = fmaxf(acc, 0.f);
    }
}

// ---------------- CSR build ----------------
__global__ void k_zero() {
    int i = blockIdx.x * blockDim.x + threadIdx.x;
    if (i < NN) { g_cnt[i] = 0; g_cur[i] = 0; }
}

__global__ void k_hist(const int* __restrict__ ei) {
    int e = blockIdx.x * blockDim.x + threadIdx.x;
    if (e < NE) atomicAdd(&g_cnt[ei[NE + e]], 1);
}

__global__ void k_scan_a() {
    __shared__ int s[256];
    int b = blockIdx.x, t = threadIdx.x;
    s[t] = (t < SCHUNK) ? g_cnt[b * SCHUNK + t] : 0;
    __syncthreads();
    for (int off = 128; off; off >>= 1) {
        if (t < off) s[t] += s[t + off];
        __syncthreads();
    }
    if (t == 0) g_bsum[b] = s[0];
}

__global__ void k_scan_b() {
    __shared__ int s[NSB];
    int t = threadIdx.x;
    for (int i = t; i < NSB; i += blockDim.x) s[i] = g_bsum[i];
    __syncthreads();
    if (t == 0) {
        int run = 0;
        for (int i = 0; i < NSB; i++) { int v = s[i]; g_bsum[i] = run; run += v; }
        g_rowptr[NN] = NE;
    }
}

__global__ void k_scan_c() {
    __shared__ int s[256];
    __shared__ int cnt_s[256];
    int b = blockIdx.x, t = threadIdx.x;
    int c = (t < SCHUNK) ? g_cnt[b * SCHUNK + t] : 0;
    cnt_s[t] = c;
    s[t] = c;
    __syncthreads();
    for (int off = 1; off < 256; off <<= 1) {
        int v = (t >= off) ? s[t - off] : 0;
        __syncthreads();
        s[t] += v;
        __syncthreads();
    }
    if (t < SCHUNK) {
        int base = g_bsum[b];
        g_rowptr[b * SCHUNK + t] = base + s[t] - cnt_s[t];  // exclusive
    }
}

__global__ void k_scatter(const int* __restrict__ ei) {
    int e = blockIdx.x * blockDim.x + threadIdx.x;
    if (e >= NE) return;
    int dst = ei[NE + e];
    int pos = g_rowptr[dst] + atomicAdd(&g_cur[dst], 1);
    g_csr_src[pos] = ei[e];
    g_csr_eid[pos] = e;
}

// ---------------- ee = relu(edge_attr@feW+feb) @ We (fused, CSR order, fp16 out)
__global__ void k_ee(const float* __restrict__ ea, const float* __restrict__ feW,
                     const float* __restrict__ feb, const float* __restrict__ We) {
    __shared__ float4 Ws4[EDIM][64];
    __shared__ float  es[32][EDIM + 1];
    __shared__ float  eas[32][2];
    int t = threadIdx.y * 32 + threadIdx.x;
    for (int i = t; i < EDIM * 64; i += 256)
        Ws4[i / 64][i % 64] = ((const float4*)We)[i];
    int e0 = blockIdx.x * 32;
    if (t < 32) {
        int eid = g_csr_eid[e0 + t];
        eas[t][0] = __ldg(&ea[eid * 2]);
        eas[t][1] = __ldg(&ea[eid * 2 + 1]);
    }
    __syncthreads();
    for (int i = t; i < 32 * EDIM; i += 256) {
        int r = i / EDIM, k = i % EDIM;
        float v = fmaf(eas[r][0], __ldg(&feW[k]),
                  fmaf(eas[r][1], __ldg(&feW[EDIM + k]), __ldg(&feb[k])));
        es[r][k] = fmaxf(v, 0.f);
    }
    __syncthreads();
    int lane = threadIdx.x, ty = threadIdx.y;
    float4 a0[4], a1[4];
#pragma unroll
    for (int r = 0; r < 4; r++) { a0[r] = make_float4(0,0,0,0); a1[r] = make_float4(0,0,0,0); }
#pragma unroll
    for (int k = 0; k < EDIM; k++) {
        float4 w0 = Ws4[k][lane * 2];
        float4 w1 = Ws4[k][lane * 2 + 1];
#pragma unroll
        for (int r = 0; r < 4; r++) {
            float ev = es[ty * 4 + r][k];
            a0[r].x = fmaf(ev, w0.x, a0[r].x); a0[r].y = fmaf(ev, w0.y, a0[r].y);
            a0[r].z = fmaf(ev, w0.z, a0[r].z); a0[r].w = fmaf(ev, w0.w, a0[r].w);
            a1[r].x = fmaf(ev, w1.x, a1[r].x); a1[r].y = fmaf(ev, w1.y, a1[r].y);
            a1[r].z = fmaf(ev, w1.z, a1[r].z); a1[r].w = fmaf(ev, w1.w, a1[r].w);
        }
    }
#pragma unroll
    for (int r = 0; r < 4; r++) {
        int e = e0 + ty * 4 + r;
        __half2 h0 = __floats2half2_rn(a0[r].x, a0[r].y);
        __half2 h1 = __floats2half2_rn(a0[r].z, a0[r].w);
        __half2 h2 = __floats2half2_rn(a1[r].x, a1[r].y);
        __half2 h3 = __floats2half2_rn(a1[r].z, a1[r].w);
        uint4 u;
        u.x = *(unsigned int*)&h0; u.y = *(unsigned int*)&h1;
        u.z = *(unsigned int*)&h2; u.w = *(unsigned int*)&h3;
        ((uint4*)(g_eecsr + (size_t)e * HD))[lane] = u;
    }
}

// ---------------- xl(fp16) = h@Wl+bl, xr(fp32) = h@Wr+br ----------------
__global__ void k_lin(const float* __restrict__ Wl, const float* __restrict__ bl,
                      const float* __restrict__ Wr, const float* __restrict__ br) {
    __shared__ float4 Ws[DD][32];
    __shared__ float  hs[32][DD];
    int t = threadIdx.y * 32 + threadIdx.x;
    int tile_c = blockIdx.y * 128;
    int isL = (tile_c < HD);
    const float* W  = isL ? Wl : Wr;
    const float* bb = isL ? bl : br;
    int cb = tile_c & (HD - 1);
    for (int i = t; i < DD * 32; i += 256) {
        int k = i / 32, q = i % 32;
        Ws[k][q] = ((const float4*)(W + k * HD + cb))[q];
    }
    int n0 = blockIdx.x * 32;
    for (int i = t; i < 32 * DD; i += 256) {
        int r = i / DD, k = i % DD;
        int n = n0 + r;
        hs[r][k] = (n < NN) ? g_h[n * DD + k] : 0.f;
    }
    __syncthreads();
    int lane = threadIdx.x, ty = threadIdx.y;
    float4 bv = ((const float4*)(bb + cb))[lane];
    float4 acc[4];
#pragma unroll
    for (int q = 0; q < 4; q++) acc[q] = bv;
#pragma unroll 16
    for (int k = 0; k < DD; k++) {
        float4 w = Ws[k][lane];
#pragma unroll
        for (int q = 0; q < 4; q++) {
            float hv = hs[ty * 4 + q][k];
            acc[q].x = fmaf(hv, w.x, acc[q].x);
            acc[q].y = fmaf(hv, w.y, acc[q].y);
            acc[q].z = fmaf(hv, w.z, acc[q].z);
            acc[q].w = fmaf(hv, w.w, acc[q].w);
        }
    }
    if (isL) {
#pragma unroll
        for (int q = 0; q < 4; q++) {
            int n = n0 + ty * 4 + q;
            if (n < NN) {
                __half2 h0 = __floats2half2_rn(acc[q].x, acc[q].y);
                __half2 h1 = __floats2half2_rn(acc[q].z, acc[q].w);
                uint2 u;
                u.x = *(unsigned int*)&h0; u.y = *(unsigned int*)&h1;
                *((uint2*)(g_xl + (size_t)n * HD + cb) + lane) = u;
            }
        }
    } else {
#pragma unroll
        for (int q = 0; q < 4; q++) {
            int n = n0 + ty * 4 + q;
            if (n < NN) ((float4*)(g_xr + (size_t)n * HD + cb))[lane] = acc[q];
        }
    }
}

// ---------------- fused: score + online softmax + aggregate + head-mean ------
// one warp per dst node; lane handles dims j = lane*8 .. lane*8+7 (head = lane>>3)
// depth-4 software pipeline + smem-staged src indices for MLP
__global__ void __launch_bounds__(256) k_fused(const float* __restrict__ att,
                        const float* __restrict__ bias, float* __restrict__ dout,
                        int writeOut) {
    __shared__ int ssrc[8][64];
    int t = threadIdx.x;
    int wid = t >> 5, lane = t & 31;
    int n = blockIdx.x * 8 + wid;
    if (n >= NN) return;

    int beg = g_rowptr[n], end = g_rowptr[n + 1];

    const float4* xr4 = (const float4*)(g_xr + (size_t)n * HD);
    float4 r0 = xr4[lane * 2], r1 = xr4[lane * 2 + 1];
    float4 av0 = __ldg(&((const float4*)att)[lane * 2]);
    float4 av1 = __ldg(&((const float4*)att)[lane * 2 + 1]);

    float m_run = -CUDART_INF_F, s_run = 0.f;
    float4 acc0 = make_float4(0, 0, 0, 0), acc1 = make_float4(0, 0, 0, 0);

#define PROCESS(XU, EU)                                                           \
    {                                                                             \
        float2 x0 = __half22float2(*(__half2*)&(XU).x);                           \
        float2 x1 = __half22float2(*(__half2*)&(XU).y);                           \
        float2 x2 = __half22float2(*(__half2*)&(XU).z);                           \
        float2 x3 = __half22float2(*(__half2*)&(XU).w);                           \
        float2 q0 = __half22float2(*(__half2*)&(EU).x);                           \
        float2 q1 = __half22float2(*(__half2*)&(EU).y);                           \
        float2 q2 = __half22float2(*(__half2*)&(EU).z);                           \
        float2 q3 = __half22float2(*(__half2*)&(EU).w);                           \
        float s = 0.f, m;                                                         \
        m = x0.x + r0.x + q0.x; m = m > 0.f ? m : 0.2f * m; s = fmaf(av0.x, m, s);\
        m = x0.y + r0.y + q0.y; m = m > 0.f ? m : 0.2f * m; s = fmaf(av0.y, m, s);\
        m = x1.x + r0.z + q1.x; m = m > 0.f ? m : 0.2f * m; s = fmaf(av0.z, m, s);\
        m = x1.y + r0.w + q1.y; m = m > 0.f ? m : 0.2f * m; s = fmaf(av0.w, m, s);\
        m = x2.x + r1.x + q2.x; m = m > 0.f ? m : 0.2f * m; s = fmaf(av1.x, m, s);\
        m = x2.y + r1.y + q2.y; m = m > 0.f ? m : 0.2f * m; s = fmaf(av1.y, m, s);\
        m = x3.x + r1.z + q3.x; m = m > 0.f ? m : 0.2f * m; s = fmaf(av1.z, m, s);\
        m = x3.y + r1.w + q3.y; m = m > 0.f ? m : 0.2f * m; s = fmaf(av1.w, m, s);\
        s += __shfl_xor_sync(0xffffffffu, s, 1);                                  \
        s += __shfl_xor_sync(0xffffffffu, s, 2);                                  \
        s += __shfl_xor_sync(0xffffffffu, s, 4);                                  \
        float nm   = fmaxf(m_run, s);                                             \
        float corr = __expf(m_run - nm);                                          \
        float w    = __expf(s - nm);                                              \
        m_run = nm;                                                               \
        s_run = fmaf(s_run, corr, w);                                             \
        acc0.x = fmaf(acc0.x, corr, w * x0.x); acc0.y = fmaf(acc0.y, corr, w * x0.y); \
        acc0.z = fmaf(acc0.z, corr, w * x1.x); acc0.w = fmaf(acc0.w, corr, w * x1.y); \
        acc1.x = fmaf(acc1.x, corr, w * x2.x); acc1.y = fmaf(acc1.y, corr, w * x2.y); \
        acc1.z = fmaf(acc1.z, corr, w * x3.x); acc1.w = fmaf(acc1.w, corr, w * x3.y); \
    }

#define LOADJ(XX, EE, j)                                                          \
    {                                                                             \
        int _src = ssrc[wid][(j)];                                                \
        XX = __ldg(&((const uint4*)(g_xl + (size_t)_src * HD))[lane]);            \
        EE = __ldcs(&((const uint4*)(g_eecsr + (size_t)(c0 + (j)) * HD))[lane]);  \
    }

    for (int c0 = beg; c0 < end; c0 += 64) {
        int c1 = min(c0 + 64, end);
        int cnt = c1 - c0;
        for (int i = lane; i < cnt; i += 32) ssrc[wid][i] = g_csr_src[c0 + i];
        __syncwarp();

        uint4 X0, X1, X2, X3, E0, E1, E2, E3;
        if (0 < cnt) LOADJ(X0, E0, 0);
        if (1 < cnt) LOADJ(X1, E1, 1);
        if (2 < cnt) LOADJ(X2, E2, 2);
        if (3 < cnt) LOADJ(X3, E3, 3);

        for (int i = 0; i < cnt; i += 4) {
            PROCESS(X0, E0);
            if (i + 4 < cnt) LOADJ(X0, E0, i + 4);
            if (i + 1 < cnt) {
                PROCESS(X1, E1);
                if (i + 5 < cnt) LOADJ(X1, E1, i + 5);
            }
            if (i + 2 < cnt) {
                PROCESS(X2, E2);
                if (i + 6 < cnt) LOADJ(X2, E2, i + 6);
            }
            if (i + 3 < cnt) {
                PROCESS(X3, E3);
                if (i + 7 < cnt) LOADJ(X3, E3, i + 7);
            }
        }
        __syncwarp();
    }
#undef LOADJ
#undef PROCESS

    float inv = (end > beg) ? 1.f / s_run : 0.f;
    float v[8];
    v[0] = acc0.x * inv; v[1] = acc0.y * inv; v[2] = acc0.z * inv; v[3] = acc0.w * inv;
    v[4] = acc1.x * inv; v[5] = acc1.y * inv; v[6] = acc1.z * inv; v[7] = acc1.w * inv;
#pragma unroll
    for (int u2 = 0; u2 < 8; u2++) {
        v[u2] += __shfl_xor_sync(0xffffffffu, v[u2], 8);
        v[u2] += __shfl_xor_sync(0xffffffffu, v[u2], 16);
    }
    if (lane < 8) {
        float4 b0 = __ldg(&((const float4*)bias)[lane * 2]);
        float4 b1 = __ldg(&((const float4*)bias)[lane * 2 + 1]);
        float4 o0, o1;
        o0.x = fmaxf(0.25f * v[0] + b0.x, 0.f);
        o0.y = fmaxf(0.25f * v[1] + b0.y, 0.f);
        o0.z = fmaxf(0.25f * v[2] + b0.z, 0.f);
        o0.w = fmaxf(0.25f * v[3] + b0.w, 0.f);
        o1.x = fmaxf(0.25f * v[4] + b1.x, 0.f);
        o1.y = fmaxf(0.25f * v[5] + b1.y, 0.f);
        o1.z = fmaxf(0.25f * v[6] + b1.z, 0.f);
        o1.w = fmaxf(0.25f * v[7] + b1.w, 0.f);
        float* outp = writeOut ? dout : g_h;
        ((float4*)(outp + n * DD))[lane * 2]     = o0;
        ((float4*)(outp + n * DD))[lane * 2 + 1] = o1;
    }
}

// ---------------- launch ----------------
extern "C" void kernel_launch(void* const* d_in, const int* in_sizes, int n_in,
                              void* d_out, int out_size) {
    const float* x   = (const float*)d_in[0];
    const float* ea  = (const float*)d_in[1];
    const int*   ei  = (const int*)  d_in[2];
    const float* fW  = (const float*)d_in[3];
    const float* fb  = (const float*)d_in[4];
    const float* feW = (const float*)d_in[5];
    const float* feb = (const float*)d_in[6];
    const float* Wl  = (const float*)d_in[7];
    const float* bl  = (const float*)d_in[8];
    const float* Wr  = (const float*)d_in[9];
    const float* br  = (const float*)d_in[10];
    const float* We  = (const float*)d_in[11];
    const float* att = (const float*)d_in[12];
    const float* bias= (const float*)d_in[13];

    // prologue
    k_h0<<<NN / 4, 256>>>(x, fW, fb);
    k_zero<<<(NN + 255) / 256, 256>>>();
    k_hist<<<(NE + 255) / 256, 256>>>(ei);
    k_scan_a<<<NSB, 256>>>();
    k_scan_b<<<1, 256>>>();
    k_scan_c<<<NSB, 256>>>();
    k_scatter<<<(NE + 255) / 256, 256>>>(ei);
    k_ee<<<NE / 32, dim3(32, 8)>>>(ea, feW, feb, We);

    for (int l = 0; l < 3; l++) {
        k_lin<<<dim3((NN + 31) / 32, 4), dim3(32, 8)>>>(Wl, bl, Wr, br);
        k_fused<<<(NN + 7) / 8, 256>>>(att, bias, (float*)d_out, l == 2 ? 1 : 0);
    }
}

// round 7
// speedup vs baseline: 1.1945x; 1.1945x over previous
#include <cuda_runtime.h>
#include <cuda_fp16.h>
#include <math_constants.h>

#define NN 50000
#define NE 800000
#define FIN 128
#define DD 64
#define HH 4
#define HD 256   // H*D
#define EDIM 20

#define SCHUNK 200
#define NSB 250   // NSB * SCHUNK == NN

// ---------------- scratch (device globals) ----------------
__device__ __half g_hh[NN * DD];         // 6.4 MB node features (fp16)
__device__ __half g_xl[NN * HD];         // 25.6 MB (fp16 gather payload)
__device__ float  g_xr[NN * HD];         // 51.2 MB
__device__ __half g_eecsr[NE * HD];      // 410 MB ee = e@We (CSR order, fp16)
__device__ __half g_Wt[512 * 64];        // [n][k] fp16: n<256 -> Wl, else Wr
__device__ int    g_cnt[NN];
__device__ int    g_cur[NN];
__device__ int    g_rowptr[NN + 1];
__device__ int    g_bsum[NSB];
__device__ int    g_csr_src[NE];
__device__ int    g_csr_eid[NE];

// ---------------- h0 = relu(x @ f_W + f_b)  (fp16 out) ----------------
__global__ void k_h0(const float* __restrict__ x, const float* __restrict__ fW,
                     const float* __restrict__ fb) {
    __shared__ float Ws[FIN * DD];
    __shared__ float xs[4][FIN];
    int t = threadIdx.x;
    for (int i = t; i < FIN * DD; i += 256) Ws[i] = fW[i];
    int n0 = blockIdx.x * 4;
    for (int i = t; i < 4 * FIN; i += 256) {
        int r = i / FIN, k = i % FIN;
        int n = n0 + r;
        xs[r][k] = (n < NN) ? x[n * FIN + k] : 0.f;
    }
    __syncthreads();
    int r = t >> 6, d = t & 63;
    int n = n0 + r;
    if (n < NN) {
        float acc = fb[d];
#pragma unroll 8
        for (int k = 0; k < FIN; k++) acc = fmaf(xs[r][k], Ws[k * DD + d], acc);
        g_hh[n * DD + d] = __float2half(fmaxf(acc, 0.f));
    }
}

// ---------------- weight transpose/convert: Wt[n][k] fp16 ----------------
__global__ void k_cvtW(const float* __restrict__ Wl, const float* __restrict__ Wr) {
    int i = blockIdx.x * 256 + threadIdx.x;
    if (i >= 512 * 64) return;
    int nn = i >> 6, k = i & 63;
    const float* W = (nn < 256) ? Wl : Wr;
    g_Wt[i] = __float2half(W[k * HD + (nn & 255)]);
}

// ---------------- CSR build ----------------
__global__ void k_zero() {
    int i = blockIdx.x * blockDim.x + threadIdx.x;
    if (i < NN) { g_cnt[i] = 0; g_cur[i] = 0; }
}

__global__ void k_hist(const int* __restrict__ ei) {
    int e = blockIdx.x * blockDim.x + threadIdx.x;
    if (e < NE) atomicAdd(&g_cnt[ei[NE + e]], 1);
}

__global__ void k_scan_a() {
    __shared__ int s[256];
    int b = blockIdx.x, t = threadIdx.x;
    s[t] = (t < SCHUNK) ? g_cnt[b * SCHUNK + t] : 0;
    __syncthreads();
    for (int off = 128; off; off >>= 1) {
        if (t < off) s[t] += s[t + off];
        __syncthreads();
    }
    if (t == 0) g_bsum[b] = s[0];
}

__global__ void k_scan_b() {
    __shared__ int s[NSB];
    int t = threadIdx.x;
    for (int i = t; i < NSB; i += blockDim.x) s[i] = g_bsum[i];
    __syncthreads();
    if (t == 0) {
        int run = 0;
        for (int i = 0; i < NSB; i++) { int v = s[i]; g_bsum[i] = run; run += v; }
        g_rowptr[NN] = NE;
    }
}

__global__ void k_scan_c() {
    __shared__ int s[256];
    __shared__ int cnt_s[256];
    int b = blockIdx.x, t = threadIdx.x;
    int c = (t < SCHUNK) ? g_cnt[b * SCHUNK + t] : 0;
    cnt_s[t] = c;
    s[t] = c;
    __syncthreads();
    for (int off = 1; off < 256; off <<= 1) {
        int v = (t >= off) ? s[t - off] : 0;
        __syncthreads();
        s[t] += v;
        __syncthreads();
    }
    if (t < SCHUNK) {
        int base = g_bsum[b];
        g_rowptr[b * SCHUNK + t] = base + s[t] - cnt_s[t];  // exclusive
    }
}

__global__ void k_scatter(const int* __restrict__ ei) {
    int e = blockIdx.x * blockDim.x + threadIdx.x;
    if (e >= NE) return;
    int dst = ei[NE + e];
    int pos = g_rowptr[dst] + atomicAdd(&g_cur[dst], 1);
    g_csr_src[pos] = ei[e];
    g_csr_eid[pos] = e;
}

// ---------------- ee = relu(edge_attr@feW+feb) @ We (fused, CSR order, fp16 out)
__global__ void k_ee(const float* __restrict__ ea, const float* __restrict__ feW,
                     const float* __restrict__ feb, const float* __restrict__ We) {
    __shared__ float4 Ws4[EDIM][64];
    __shared__ float  es[32][EDIM + 1];
    __shared__ float  eas[32][2];
    int t = threadIdx.y * 32 + threadIdx.x;
    for (int i = t; i < EDIM * 64; i += 256)
        Ws4[i / 64][i % 64] = ((const float4*)We)[i];
    int e0 = blockIdx.x * 32;
    if (t < 32) {
        int eid = g_csr_eid[e0 + t];
        eas[t][0] = __ldg(&ea[eid * 2]);
        eas[t][1] = __ldg(&ea[eid * 2 + 1]);
    }
    __syncthreads();
    for (int i = t; i < 32 * EDIM; i += 256) {
        int r = i / EDIM, k = i % EDIM;
        float v = fmaf(eas[r][0], __ldg(&feW[k]),
                  fmaf(eas[r][1], __ldg(&feW[EDIM + k]), __ldg(&feb[k])));
        es[r][k] = fmaxf(v, 0.f);
    }
    __syncthreads();
    int lane = threadIdx.x, ty = threadIdx.y;
    float4 a0[4], a1[4];
#pragma unroll
    for (int r = 0; r < 4; r++) { a0[r] = make_float4(0,0,0,0); a1[r] = make_float4(0,0,0,0); }
#pragma unroll
    for (int k = 0; k < EDIM; k++) {
        float4 w0 = Ws4[k][lane * 2];
        float4 w1 = Ws4[k][lane * 2 + 1];
#pragma unroll
        for (int r = 0; r < 4; r++) {
            float ev = es[ty * 4 + r][k];
            a0[r].x = fmaf(ev, w0.x, a0[r].x); a0[r].y = fmaf(ev, w0.y, a0[r].y);
            a0[r].z = fmaf(ev, w0.z, a0[r].z); a0[r].w = fmaf(ev, w0.w, a0[r].w);
            a1[r].x = fmaf(ev, w1.x, a1[r].x); a1[r].y = fmaf(ev, w1.y, a1[r].y);
            a1[r].z = fmaf(ev, w1.z, a1[r].z); a1[r].w = fmaf(ev, w1.w, a1[r].w);
        }
    }
#pragma unroll
    for (int r = 0; r < 4; r++) {
        int e = e0 + ty * 4 + r;
        __half2 h0 = __floats2half2_rn(a0[r].x, a0[r].y);
        __half2 h1 = __floats2half2_rn(a0[r].z, a0[r].w);
        __half2 h2 = __floats2half2_rn(a1[r].x, a1[r].y);
        __half2 h3 = __floats2half2_rn(a1[r].z, a1[r].w);
        uint4 u;
        u.x = *(unsigned int*)&h0; u.y = *(unsigned int*)&h1;
        u.z = *(unsigned int*)&h2; u.w = *(unsigned int*)&h3;
        ((uint4*)(g_eecsr + (size_t)e * HD))[lane] = u;
    }
}

// ---------------- tensor-core GEMM: [xl|xr] = hh @ [Wl|Wr] + bias ----------
// grid (ceil(NN/128), 8); block 256 (8 warps). Warp w: rows w*16..w*16+15,
// all 64 cols of this block's n-tile. K = 64.
__global__ void __launch_bounds__(256) k_lin_tc(const float* __restrict__ bl,
                                                const float* __restrict__ br) {
    __shared__ __half As[128][72];   // h tile, padded
    __shared__ __half Bs[64][72];    // Wt tile, padded
    int t = threadIdx.x;
    int warp = t >> 5, lane = t & 31;
    int m0 = blockIdx.x * 128;
    int n0 = blockIdx.y * 64;        // global col in [0,512)

    // load A (guard rows >= NN with zeros)
    for (int i = t; i < 128 * 8; i += 256) {
        int r = i >> 3, c = i & 7;
        uint4 v = make_uint4(0, 0, 0, 0);
        if (m0 + r < NN) v = ((const uint4*)(g_hh + (size_t)(m0 + r) * DD))[c];
        *(uint4*)&As[r][c * 8] = v;
    }
    // load B
    for (int i = t; i < 64 * 8; i += 256) {
        int r = i >> 3, c = i & 7;
        *(uint4*)&Bs[r][c * 8] = ((const uint4*)(g_Wt + (size_t)(n0 + r) * 64))[c];
    }
    __syncthreads();

    float acc[8][4];
#pragma unroll
    for (int j = 0; j < 8; j++)
#pragma unroll
        for (int q = 0; q < 4; q++) acc[j][q] = 0.f;

#pragma unroll
    for (int k0 = 0; k0 < 64; k0 += 16) {
        unsigned a0, a1, a2, a3;
        {
            int ar = warp * 16 + (lane & 15);
            int ac = k0 + ((lane >> 4) << 3);
            unsigned aaddr = (unsigned)__cvta_generic_to_shared(&As[ar][ac]);
            asm volatile("ldmatrix.sync.aligned.m8n8.x4.shared.b16 {%0,%1,%2,%3}, [%4];"
                         : "=r"(a0), "=r"(a1), "=r"(a2), "=r"(a3) : "r"(aaddr));
        }
#pragma unroll
        for (int j = 0; j < 8; j++) {
            unsigned b0, b1;
            {
                int brow = j * 8 + (lane & 7);
                int bcol = k0 + (((lane >> 3) & 1) << 3);
                unsigned baddr = (unsigned)__cvta_generic_to_shared(&Bs[brow][bcol]);
                asm volatile("ldmatrix.sync.aligned.m8n8.x2.shared.b16 {%0,%1}, [%2];"
                             : "=r"(b0), "=r"(b1) : "r"(baddr));
            }
            asm volatile(
                "mma.sync.aligned.m16n8k16.row.col.f32.f16.f16.f32 "
                "{%0,%1,%2,%3}, {%4,%5,%6,%7}, {%8,%9}, {%0,%1,%2,%3};"
                : "+f"(acc[j][0]), "+f"(acc[j][1]), "+f"(acc[j][2]), "+f"(acc[j][3])
                : "r"(a0), "r"(a1), "r"(a2), "r"(a3), "r"(b0), "r"(b1));
        }
    }

    // epilogue
    int row_base = m0 + warp * 16 + (lane >> 2);
    int isL = (n0 < HD);
    const float* bb = isL ? bl : br;
    int cb = n0 & (HD - 1);
#pragma unroll
    for (int j = 0; j < 8; j++) {
        int col = cb + j * 8 + (lane & 3) * 2;   // within [0,256)
        float bv0 = __ldg(&bb[col]), bv1 = __ldg(&bb[col + 1]);
#pragma unroll
        for (int half = 0; half < 2; half++) {
            int row = row_base + half * 8;
            if (row >= NN) continue;
            float v0 = acc[j][half * 2 + 0] + bv0;
            float v1 = acc[j][half * 2 + 1] + bv1;
            if (isL) {
                __half2 hv = __floats2half2_rn(v0, v1);
                *(__half2*)(g_xl + (size_t)row * HD + col) = hv;
            } else {
                *(float2*)(g_xr + (size_t)row * HD + col) = make_float2(v0, v1);
            }
        }
    }
}

// ---------------- fused: score + online softmax + aggregate + head-mean ------
// one warp per dst node; lane handles dims j = lane*8 .. lane*8+7 (head = lane>>3)
__global__ void __launch_bounds__(256) k_fused(const float* __restrict__ att,
                        const float* __restrict__ bias, float* __restrict__ dout,
                        int writeOut) {
    __shared__ int ssrc[8][64];
    int t = threadIdx.x;
    int wid = t >> 5, lane = t & 31;
    int n = blockIdx.x * 8 + wid;
    if (n >= NN) return;

    int beg = g_rowptr[n], end = g_rowptr[n + 1];

    const float4* xr4 = (const float4*)(g_xr + (size_t)n * HD);
    float4 r0 = xr4[lane * 2], r1 = xr4[lane * 2 + 1];
    float4 av0 = __ldg(&((const float4*)att)[lane * 2]);
    float4 av1 = __ldg(&((const float4*)att)[lane * 2 + 1]);

    float m_run = -CUDART_INF_F, s_run = 0.f;
    float4 acc0 = make_float4(0, 0, 0, 0), acc1 = make_float4(0, 0, 0, 0);

#define PROCESS(XU, EU)                                                           \
    {                                                                             \
        float2 x0 = __half22float2(*(__half2*)&(XU).x);                           \
        float2 x1 = __half22float2(*(__half2*)&(XU).y);                           \
        float2 x2 = __half22float2(*(__half2*)&(XU).z);                           \
        float2 x3 = __half22float2(*(__half2*)&(XU).w);                           \
        float2 q0 = __half22float2(*(__half2*)&(EU).x);                           \
        float2 q1 = __half22float2(*(__half2*)&(EU).y);                           \
        float2 q2 = __half22float2(*(__half2*)&(EU).z);                           \
        float2 q3 = __half22float2(*(__half2*)&(EU).w);                           \
        float s = 0.f, m;                                                         \
        m = x0.x + r0.x + q0.x; m = m > 0.f ? m : 0.2f * m; s = fmaf(av0.x, m, s);\
        m = x0.y + r0.y + q0.y; m = m > 0.f ? m : 0.2f * m; s = fmaf(av0.y, m, s);\
        m = x1.x + r0.z + q1.x; m = m > 0.f ? m : 0.2f * m; s = fmaf(av0.z, m, s);\
        m = x1.y + r0.w + q1.y; m = m > 0.f ? m : 0.2f * m; s = fmaf(av0.w, m, s);\
        m = x2.x + r1.x + q2.x; m = m > 0.f ? m : 0.2f * m; s = fmaf(av1.x, m, s);\
        m = x2.y + r1.y + q2.y; m = m > 0.f ? m : 0.2f * m; s = fmaf(av1.y, m, s);\
        m = x3.x + r1.z + q3.x; m = m > 0.f ? m : 0.2f * m; s = fmaf(av1.z, m, s);\
        m = x3.y + r1.w + q3.y; m = m > 0.f ? m : 0.2f * m; s = fmaf(av1.w, m, s);\
        s += __shfl_xor_sync(0xffffffffu, s, 1);                                  \
        s += __shfl_xor_sync(0xffffffffu, s, 2);                                  \
        s += __shfl_xor_sync(0xffffffffu, s, 4);                                  \
        float nm   = fmaxf(m_run, s);                                             \
        float corr = __expf(m_run - nm);                                          \
        float w    = __expf(s - nm);                                              \
        m_run = nm;                                                               \
        s_run = fmaf(s_run, corr, w);                                             \
        acc0.x = fmaf(acc0.x, corr, w * x0.x); acc0.y = fmaf(acc0.y, corr, w * x0.y); \
        acc0.z = fmaf(acc0.z, corr, w * x1.x); acc0.w = fmaf(acc0.w, corr, w * x1.y); \
        acc1.x = fmaf(acc1.x, corr, w * x2.x); acc1.y = fmaf(acc1.y, corr, w * x2.y); \
        acc1.z = fmaf(acc1.z, corr, w * x3.x); acc1.w = fmaf(acc1.w, corr, w * x3.y); \
    }

#define LOADJ(XX, EE, j)                                                          \
    {                                                                             \
        int _src = ssrc[wid][(j)];                                                \
        XX = __ldg(&((const uint4*)(g_xl + (size_t)_src * HD))[lane]);            \
        EE = __ldcs(&((const uint4*)(g_eecsr + (size_t)(c0 + (j)) * HD))[lane]);  \
    }

    for (int c0 = beg; c0 < end; c0 += 64) {
        int c1 = min(c0 + 64, end);
        int cnt = c1 - c0;
        for (int i = lane; i < cnt; i += 32) ssrc[wid][i] = g_csr_src[c0 + i];
        __syncwarp();

        uint4 X0, X1, X2, X3, E0, E1, E2, E3;
        if (0 < cnt) LOADJ(X0, E0, 0);
        if (1 < cnt) LOADJ(X1, E1, 1);
        if (2 < cnt) LOADJ(X2, E2, 2);
        if (3 < cnt) LOADJ(X3, E3, 3);

        for (int i = 0; i < cnt; i += 4) {
            PROCESS(X0, E0);
            if (i + 4 < cnt) LOADJ(X0, E0, i + 4);
            if (i + 1 < cnt) {
                PROCESS(X1, E1);
                if (i + 5 < cnt) LOADJ(X1, E1, i + 5);
            }
            if (i + 2 < cnt) {
                PROCESS(X2, E2);
                if (i + 6 < cnt) LOADJ(X2, E2, i + 6);
            }
            if (i + 3 < cnt) {
                PROCESS(X3, E3);
                if (i + 7 < cnt) LOADJ(X3, E3, i + 7);
            }
        }
        __syncwarp();
    }
#undef LOADJ
#undef PROCESS

    float inv = (end > beg) ? 1.f / s_run : 0.f;
    float v[8];
    v[0] = acc0.x * inv; v[1] = acc0.y * inv; v[2] = acc0.z * inv; v[3] = acc0.w * inv;
    v[4] = acc1.x * inv; v[5] = acc1.y * inv; v[6] = acc1.z * inv; v[7] = acc1.w * inv;
#pragma unroll
    for (int u2 = 0; u2 < 8; u2++) {
        v[u2] += __shfl_xor_sync(0xffffffffu, v[u2], 8);
        v[u2] += __shfl_xor_sync(0xffffffffu, v[u2], 16);
    }
    if (lane < 8) {
        float4 b0 = __ldg(&((const float4*)bias)[lane * 2]);
        float4 b1 = __ldg(&((const float4*)bias)[lane * 2 + 1]);
        float o[8];
        o[0] = fmaxf(0.25f * v[0] + b0.x, 0.f);
        o[1] = fmaxf(0.25f * v[1] + b0.y, 0.f);
        o[2] = fmaxf(0.25f * v[2] + b0.z, 0.f);
        o[3] = fmaxf(0.25f * v[3] + b0.w, 0.f);
        o[4] = fmaxf(0.25f * v[4] + b1.x, 0.f);
        o[5] = fmaxf(0.25f * v[5] + b1.y, 0.f);
        o[6] = fmaxf(0.25f * v[6] + b1.z, 0.f);
        o[7] = fmaxf(0.25f * v[7] + b1.w, 0.f);
        if (writeOut) {
            ((float4*)(dout + n * DD))[lane * 2]     = make_float4(o[0], o[1], o[2], o[3]);
            ((float4*)(dout + n * DD))[lane * 2 + 1] = make_float4(o[4], o[5], o[6], o[7]);
        } else {
            __half2 h0 = __floats2half2_rn(o[0], o[1]);
            __half2 h1 = __floats2half2_rn(o[2], o[3]);
            __half2 h2 = __floats2half2_rn(o[4], o[5]);
            __half2 h3 = __floats2half2_rn(o[6], o[7]);
            uint4 u;
            u.x = *(unsigned int*)&h0; u.y = *(unsigned int*)&h1;
            u.z = *(unsigned int*)&h2; u.w = *(unsigned int*)&h3;
            ((uint4*)(g_hh + (size_t)n * DD))[lane] = u;
        }
    }
}

// ---------------- launch ----------------
extern "C" void kernel_launch(void* const* d_in, const int* in_sizes, int n_in,
                              void* d_out, int out_size) {
    const float* x   = (const float*)d_in[0];
    const float* ea  = (const float*)d_in[1];
    const int*   ei  = (const int*)  d_in[2];
    const float* fW  = (const float*)d_in[3];
    const float* fb  = (const float*)d_in[4];
    const float* feW = (const float*)d_in[5];
    const float* feb = (const float*)d_in[6];
    const float* Wl  = (const float*)d_in[7];
    const float* bl  = (const float*)d_in[8];
    const float* Wr  = (const float*)d_in[9];
    const float* br  = (const float*)d_in[10];
    const float* We  = (const float*)d_in[11];
    const float* att = (const float*)d_in[12];
    const float* bias= (const float*)d_in[13];

    // prologue
    k_h0<<<NN / 4, 256>>>(x, fW, fb);
    k_cvtW<<<(512 * 64 + 255) / 256, 256>>>(Wl, Wr);
    k_zero<<<(NN + 255) / 256, 256>>>();
    k_hist<<<(NE + 255) / 256, 256>>>(ei);
    k_scan_a<<<NSB, 256>>>();
    k_scan_b<<<1, 256>>>();
    k_scan_c<<<NSB, 256>>>();
    k_scatter<<<(NE + 255) / 256, 256>>>(ei);
    k_ee<<<NE / 32, dim3(32, 8)>>>(ea, feW, feb, We);

    for (int l = 0; l < 3; l++) {
        k_lin_tc<<<dim3((NN + 127) / 128, 8), 256>>>(bl, br);
        k_fused<<<(NN + 7) / 8, 256>>>(att, bias, (float*)d_out, l == 2 ? 1 : 0);
    }
}

// round 8
// speedup vs baseline: 1.4834x; 1.2418x over previous
#include <cuda_runtime.h>
#include <cuda_fp16.h>
#include <math_constants.h>

#define NN 50000
#define NE 800000
#define FIN 128
#define DD 64
#define HH 4
#define HD 256   // H*D
#define EDIM 20

#define SCHUNK 200
#define NSB 250   // NSB * SCHUNK == NN

// ---------------- scratch (device globals) ----------------
__device__ __half g_hh[NN * DD];         // 6.4 MB node features (fp16)
__device__ __half g_xl[NN * HD];         // 25.6 MB (fp16 gather payload)
__device__ float  g_xr[NN * HD];         // 51.2 MB
__device__ __half g_eecsr[NE * HD];      // 410 MB ee = e@We (CSR order, fp16)
__device__ __half g_Wt[512 * 64];        // [n][k] fp16: n<256 -> Wl, else Wr
__device__ __half g_Wep[256 * 32];       // [n][k] fp16: We^T zero-padded K 20->32
__device__ int    g_cnt[NN];
__device__ int    g_cur[NN];
__device__ int    g_rowptr[NN + 1];
__device__ int    g_bsum[NSB];
__device__ int    g_csr_src[NE];
__device__ int    g_csr_eid[NE];

// ---------------- h0 = relu(x @ f_W + f_b)  (fp16 out), 16 rows/block -------
// also zeroes g_cnt/g_cur (grid covers NN)
__global__ void k_h0(const float* __restrict__ x, const float* __restrict__ fW,
                     const float* __restrict__ fb) {
    __shared__ float Ws[FIN * DD];    // 32 KB
    __shared__ float xs[16][FIN];     // 8 KB
    int t = threadIdx.x;
    int gi = blockIdx.x * 256 + t;
    if (gi < NN) { g_cnt[gi] = 0; g_cur[gi] = 0; }
    for (int i = t; i < FIN * DD; i += 256) Ws[i] = fW[i];
    int n0 = blockIdx.x * 16;
    for (int i = t; i < 16 * FIN; i += 256) {
        int r = i / FIN, k = i % FIN;
        int n = n0 + r;
        xs[r][k] = (n < NN) ? x[n * FIN + k] : 0.f;
    }
    __syncthreads();
    int rg = t >> 6, d = t & 63;
    float b = fb[d];
    float acc[4] = {b, b, b, b};
#pragma unroll 8
    for (int k = 0; k < FIN; k++) {
        float w = Ws[k * DD + d];
#pragma unroll
        for (int q = 0; q < 4; q++) acc[q] = fmaf(xs[rg * 4 + q][k], w, acc[q]);
    }
#pragma unroll
    for (int q = 0; q < 4; q++) {
        int n = n0 + rg * 4 + q;
        if (n < NN) g_hh[n * DD + d] = __float2half(fmaxf(acc[q], 0.f));
    }
}

// ---------------- weight convert: Wt[n][k], Wep[n][k] fp16 ----------------
__global__ void k_cvt(const float* __restrict__ Wl, const float* __restrict__ Wr,
                      const float* __restrict__ We) {
    int i = blockIdx.x * 256 + threadIdx.x;
    if (i < 512 * 64) {
        int nn = i >> 6, k = i & 63;
        const float* W = (nn < 256) ? Wl : Wr;
        g_Wt[i] = __float2half(W[k * HD + (nn & 255)]);
    }
    int j = i - 512 * 64;
    if (j >= 0 && j < 256 * 32) {
        int nn = j >> 5, k = j & 31;
        g_Wep[j] = (k < EDIM) ? __float2half(We[k * HD + nn]) : __half(0);
    }
}

// ---------------- CSR build ----------------
__global__ void k_hist(const int* __restrict__ ei) {
    int e = blockIdx.x * blockDim.x + threadIdx.x;
    if (e < NE) atomicAdd(&g_cnt[ei[NE + e]], 1);
}

__global__ void k_scan_a() {
    __shared__ int s[256];
    int b = blockIdx.x, t = threadIdx.x;
    s[t] = (t < SCHUNK) ? g_cnt[b * SCHUNK + t] : 0;
    __syncthreads();
    for (int off = 128; off; off >>= 1) {
        if (t < off) s[t] += s[t + off];
        __syncthreads();
    }
    if (t == 0) g_bsum[b] = s[0];
}

__global__ void k_scan_b() {
    __shared__ int s[NSB];
    int t = threadIdx.x;
    for (int i = t; i < NSB; i += blockDim.x) s[i] = g_bsum[i];
    __syncthreads();
    if (t == 0) {
        int run = 0;
        for (int i = 0; i < NSB; i++) { int v = s[i]; g_bsum[i] = run; run += v; }
        g_rowptr[NN] = NE;
    }
}

__global__ void k_scan_c() {
    __shared__ int s[256];
    __shared__ int cnt_s[256];
    int b = blockIdx.x, t = threadIdx.x;
    int c = (t < SCHUNK) ? g_cnt[b * SCHUNK + t] : 0;
    cnt_s[t] = c;
    s[t] = c;
    __syncthreads();
    for (int off = 1; off < 256; off <<= 1) {
        int v = (t >= off) ? s[t - off] : 0;
        __syncthreads();
        s[t] += v;
        __syncthreads();
    }
    if (t < SCHUNK) {
        int base = g_bsum[b];
        g_rowptr[b * SCHUNK + t] = base + s[t] - cnt_s[t];  // exclusive
    }
}

__global__ void k_scatter(const int* __restrict__ ei) {
    int e = blockIdx.x * blockDim.x + threadIdx.x;
    if (e >= NE) return;
    int dst = ei[NE + e];
    int pos = g_rowptr[dst] + atomicAdd(&g_cur[dst], 1);
    g_csr_src[pos] = ei[e];
    g_csr_eid[pos] = e;
}

// ---------------- ee = relu(ea@feW+feb) @ We  — tensor cores ---------------
// grid (NE/128, 4); block 256 (8 warps). Block: 128 edges x 64 cols.
// A[128x32] fp16 edge-emb (padded K), B = Wep[n0..n0+63][32].
__global__ void __launch_bounds__(256) k_ee_tc(const float* __restrict__ ea,
                                               const float* __restrict__ feW,
                                               const float* __restrict__ feb) {
    __shared__ float  eas[128][2];
    __shared__ __half As[128][40];   // 10 KB (row stride 80B, 16B-aligned)
    __shared__ __half Bs[64][40];    // 5.1 KB
    __shared__ __half Os[128][72];   // 18.4 KB output staging (stride 144B)
    int t = threadIdx.x;
    int warp = t >> 5, lane = t & 31;
    int e0 = blockIdx.x * 128;
    int n0 = blockIdx.y * 64;

    if (t < 128) {
        int eid = g_csr_eid[e0 + t];
        float2 a = __ldg(&((const float2*)ea)[eid]);
        eas[t][0] = a.x; eas[t][1] = a.y;
    }
    // load B tile
    for (int i = t; i < 64 * 4; i += 256) {
        int r = i >> 2, c = i & 3;
        *(uint4*)&Bs[r][c * 8] = ((const uint4*)(g_Wep + (size_t)(n0 + r) * 32))[c];
    }
    __syncthreads();
    // compute A tile (edge MLP), zero-pad k >= 20
    for (int i = t; i < 128 * 32; i += 256) {
        int r = i >> 5, k = i & 31;
        __half v = __half(0);
        if (k < EDIM) {
            float f = fmaf(eas[r][0], __ldg(&feW[k]),
                      fmaf(eas[r][1], __ldg(&feW[EDIM + k]), __ldg(&feb[k])));
            v = __float2half(fmaxf(f, 0.f));
        }
        As[r][k] = v;
    }
    __syncthreads();

    float acc[8][4];
#pragma unroll
    for (int j = 0; j < 8; j++)
#pragma unroll
        for (int q = 0; q < 4; q++) acc[j][q] = 0.f;

#pragma unroll
    for (int k0 = 0; k0 < 32; k0 += 16) {
        unsigned a0, a1, a2, a3;
        {
            int ar = warp * 16 + (lane & 15);
            int ac = k0 + ((lane >> 4) << 3);
            unsigned aaddr = (unsigned)__cvta_generic_to_shared(&As[ar][ac]);
            asm volatile("ldmatrix.sync.aligned.m8n8.x4.shared.b16 {%0,%1,%2,%3}, [%4];"
                         : "=r"(a0), "=r"(a1), "=r"(a2), "=r"(a3) : "r"(aaddr));
        }
#pragma unroll
        for (int j = 0; j < 8; j++) {
            unsigned b0, b1;
            {
                int brow = j * 8 + (lane & 7);
                int bcol = k0 + (((lane >> 3) & 1) << 3);
                unsigned baddr = (unsigned)__cvta_generic_to_shared(&Bs[brow][bcol]);
                asm volatile("ldmatrix.sync.aligned.m8n8.x2.shared.b16 {%0,%1}, [%2];"
                             : "=r"(b0), "=r"(b1) : "r"(baddr));
            }
            asm volatile(
                "mma.sync.aligned.m16n8k16.row.col.f32.f16.f16.f32 "
                "{%0,%1,%2,%3}, {%4,%5,%6,%7}, {%8,%9}, {%0,%1,%2,%3};"
                : "+f"(acc[j][0]), "+f"(acc[j][1]), "+f"(acc[j][2]), "+f"(acc[j][3])
                : "r"(a0), "r"(a1), "r"(a2), "r"(a3), "r"(b0), "r"(b1));
        }
    }

    // stage to smem (half) then coalesced store
    int row_base = warp * 16 + (lane >> 2);
#pragma unroll
    for (int j = 0; j < 8; j++) {
        int col = j * 8 + (lane & 3) * 2;
        *(__half2*)&Os[row_base][col]     = __floats2half2_rn(acc[j][0], acc[j][1]);
        *(__half2*)&Os[row_base + 8][col] = __floats2half2_rn(acc[j][2], acc[j][3]);
    }
    __syncthreads();
    for (int i = t; i < 128 * 8; i += 256) {
        int r = i >> 3, c = i & 7;
        ((uint4*)(g_eecsr + (size_t)(e0 + r) * HD + n0))[c] = *(uint4*)&Os[r][c * 8];
    }
}

// ---------------- tensor-core GEMM: [xl|xr] = hh @ [Wl|Wr] + bias ----------
__global__ void __launch_bounds__(256) k_lin_tc(const float* __restrict__ bl,
                                                const float* __restrict__ br) {
    __shared__ __half As[128][72];
    __shared__ __half Bs[64][72];
    int t = threadIdx.x;
    int warp = t >> 5, lane = t & 31;
    int m0 = blockIdx.x * 128;
    int n0 = blockIdx.y * 64;

    for (int i = t; i < 128 * 8; i += 256) {
        int r = i >> 3, c = i & 7;
        uint4 v = make_uint4(0, 0, 0, 0);
        if (m0 + r < NN) v = ((const uint4*)(g_hh + (size_t)(m0 + r) * DD))[c];
        *(uint4*)&As[r][c * 8] = v;
    }
    for (int i = t; i < 64 * 8; i += 256) {
        int r = i >> 3, c = i & 7;
        *(uint4*)&Bs[r][c * 8] = ((const uint4*)(g_Wt + (size_t)(n0 + r) * 64))[c];
    }
    __syncthreads();

    float acc[8][4];
#pragma unroll
    for (int j = 0; j < 8; j++)
#pragma unroll
        for (int q = 0; q < 4; q++) acc[j][q] = 0.f;

#pragma unroll
    for (int k0 = 0; k0 < 64; k0 += 16) {
        unsigned a0, a1, a2, a3;
        {
            int ar = warp * 16 + (lane & 15);
            int ac = k0 + ((lane >> 4) << 3);
            unsigned aaddr = (unsigned)__cvta_generic_to_shared(&As[ar][ac]);
            asm volatile("ldmatrix.sync.aligned.m8n8.x4.shared.b16 {%0,%1,%2,%3}, [%4];"
                         : "=r"(a0), "=r"(a1), "=r"(a2), "=r"(a3) : "r"(aaddr));
        }
#pragma unroll
        for (int j = 0; j < 8; j++) {
            unsigned b0, b1;
            {
                int brow = j * 8 + (lane & 7);
                int bcol = k0 + (((lane >> 3) & 1) << 3);
                unsigned baddr = (unsigned)__cvta_generic_to_shared(&Bs[brow][bcol]);
                asm volatile("ldmatrix.sync.aligned.m8n8.x2.shared.b16 {%0,%1}, [%2];"
                             : "=r"(b0), "=r"(b1) : "r"(baddr));
            }
            asm volatile(
                "mma.sync.aligned.m16n8k16.row.col.f32.f16.f16.f32 "
                "{%0,%1,%2,%3}, {%4,%5,%6,%7}, {%8,%9}, {%0,%1,%2,%3};"
                : "+f"(acc[j][0]), "+f"(acc[j][1]), "+f"(acc[j][2]), "+f"(acc[j][3])
                : "r"(a0), "r"(a1), "r"(a2), "r"(a3), "r"(b0), "r"(b1));
        }
    }

    int row_base = m0 + warp * 16 + (lane >> 2);
    int isL = (n0 < HD);
    const float* bb = isL ? bl : br;
    int cb = n0 & (HD - 1);
#pragma unroll
    for (int j = 0; j < 8; j++) {
        int col = cb + j * 8 + (lane & 3) * 2;
        float bv0 = __ldg(&bb[col]), bv1 = __ldg(&bb[col + 1]);
#pragma unroll
        for (int half = 0; half < 2; half++) {
            int row = row_base + half * 8;
            if (row >= NN) continue;
            float v0 = acc[j][half * 2 + 0] + bv0;
            float v1 = acc[j][half * 2 + 1] + bv1;
            if (isL) {
                *(__half2*)(g_xl + (size_t)row * HD + col) = __floats2half2_rn(v0, v1);
            } else {
                *(float2*)(g_xr + (size_t)row * HD + col) = make_float2(v0, v1);
            }
        }
    }
}

// ---------------- fused: score + online softmax + aggregate + head-mean ------
__global__ void __launch_bounds__(256) k_fused(const float* __restrict__ att,
                        const float* __restrict__ bias, float* __restrict__ dout,
                        int writeOut) {
    __shared__ int ssrc[8][64];
    int t = threadIdx.x;
    int wid = t >> 5, lane = t & 31;
    int n = blockIdx.x * 8 + wid;
    if (n >= NN) return;

    int beg = g_rowptr[n], end = g_rowptr[n + 1];

    const float4* xr4 = (const float4*)(g_xr + (size_t)n * HD);
    float4 r0 = xr4[lane * 2], r1 = xr4[lane * 2 + 1];
    float4 av0 = __ldg(&((const float4*)att)[lane * 2]);
    float4 av1 = __ldg(&((const float4*)att)[lane * 2 + 1]);

    float m_run = -CUDART_INF_F, s_run = 0.f;
    float4 acc0 = make_float4(0, 0, 0, 0), acc1 = make_float4(0, 0, 0, 0);

#define PROCESS(XU, EU)                                                           \
    {                                                                             \
        float2 x0 = __half22float2(*(__half2*)&(XU).x);                           \
        float2 x1 = __half22float2(*(__half2*)&(XU).y);                           \
        float2 x2 = __half22float2(*(__half2*)&(XU).z);                           \
        float2 x3 = __half22float2(*(__half2*)&(XU).w);                           \
        float2 q0 = __half22float2(*(__half2*)&(EU).x);                           \
        float2 q1 = __half22float2(*(__half2*)&(EU).y);                           \
        float2 q2 = __half22float2(*(__half2*)&(EU).z);                           \
        float2 q3 = __half22float2(*(__half2*)&(EU).w);                           \
        float s = 0.f, m;                                                         \
        m = x0.x + r0.x + q0.x; m = m > 0.f ? m : 0.2f * m; s = fmaf(av0.x, m, s);\
        m = x0.y + r0.y + q0.y; m = m > 0.f ? m : 0.2f * m; s = fmaf(av0.y, m, s);\
        m = x1.x + r0.z + q1.x; m = m > 0.f ? m : 0.2f * m; s = fmaf(av0.z, m, s);\
        m = x1.y + r0.w + q1.y; m = m > 0.f ? m : 0.2f * m; s = fmaf(av0.w, m, s);\
        m = x2.x + r1.x + q2.x; m = m > 0.f ? m : 0.2f * m; s = fmaf(av1.x, m, s);\
        m = x2.y + r1.y + q2.y; m = m > 0.f ? m : 0.2f * m; s = fmaf(av1.y, m, s);\
        m = x3.x + r1.z + q3.x; m = m > 0.f ? m : 0.2f * m; s = fmaf(av1.z, m, s);\
        m = x3.y + r1.w + q3.y; m = m > 0.f ? m : 0.2f * m; s = fmaf(av1.w, m, s);\
        s += __shfl_xor_sync(0xffffffffu, s, 1);                                  \
        s += __shfl_xor_sync(0xffffffffu, s, 2);                                  \
        s += __shfl_xor_sync(0xffffffffu, s, 4);                                  \
        float nm   = fmaxf(m_run, s);                                             \
        float corr = __expf(m_run - nm);                                          \
        float w    = __expf(s - nm);                                              \
        m_run = nm;                                                               \
        s_run = fmaf(s_run, corr, w);                                             \
        acc0.x = fmaf(acc0.x, corr, w * x0.x); acc0.y = fmaf(acc0.y, corr, w * x0.y); \
        acc0.z = fmaf(acc0.z, corr, w * x1.x); acc0.w = fmaf(acc0.w, corr, w * x1.y); \
        acc1.x = fmaf(acc1.x, corr, w * x2.x); acc1.y = fmaf(acc1.y, corr, w * x2.y); \
        acc1.z = fmaf(acc1.z, corr, w * x3.x); acc1.w = fmaf(acc1.w, corr, w * x3.y); \
    }

#define LOADJ(XX, EE, j)                                                          \
    {                                                                             \
        int _src = ssrc[wid][(j)];                                                \
        XX = __ldg(&((const uint4*)(g_xl + (size_t)_src * HD))[lane]);            \
        EE = __ldcs(&((const uint4*)(g_eecsr + (size_t)(c0 + (j)) * HD))[lane]);  \
    }

    for (int c0 = beg; c0 < end; c0 += 64) {
        int c1 = min(c0 + 64, end);
        int cnt = c1 - c0;
        for (int i = lane; i < cnt; i += 32) ssrc[wid][i] = g_csr_src[c0 + i];
        __syncwarp();

        uint4 X0, X1, X2, X3, E0, E1, E2, E3;
        if (0 < cnt) LOADJ(X0, E0, 0);
        if (1 < cnt) LOADJ(X1, E1, 1);
        if (2 < cnt) LOADJ(X2, E2, 2);
        if (3 < cnt) LOADJ(X3, E3, 3);

        for (int i = 0; i < cnt; i += 4) {
            PROCESS(X0, E0);
            if (i + 4 < cnt) LOADJ(X0, E0, i + 4);
            if (i + 1 < cnt) {
                PROCESS(X1, E1);
                if (i + 5 < cnt) LOADJ(X1, E1, i + 5);
            }
            if (i + 2 < cnt) {
                PROCESS(X2, E2);
                if (i + 6 < cnt) LOADJ(X2, E2, i + 6);
            }
            if (i + 3 < cnt) {
                PROCESS(X3, E3);
                if (i + 7 < cnt) LOADJ(X3, E3, i + 7);
            }
        }
        __syncwarp();
    }
#undef LOADJ
#undef PROCESS

    float inv = (end > beg) ? 1.f / s_run : 0.f;
    float v[8];
    v[0] = acc0.x * inv; v[1] = acc0.y * inv; v[2] = acc0.z * inv; v[3] = acc0.w * inv;
    v[4] = acc1.x * inv; v[5] = acc1.y * inv; v[6] = acc1.z * inv; v[7] = acc1.w * inv;
#pragma unroll
    for (int u2 = 0; u2 < 8; u2++) {
        v[u2] += __shfl_xor_sync(0xffffffffu, v[u2], 8);
        v[u2] += __shfl_xor_sync(0xffffffffu, v[u2], 16);
    }
    if (lane < 8) {
        float4 b0 = __ldg(&((const float4*)bias)[lane * 2]);
        float4 b1 = __ldg(&((const float4*)bias)[lane * 2 + 1]);
        float o[8];
        o[0] = fmaxf(0.25f * v[0] + b0.x, 0.f);
        o[1] = fmaxf(0.25f * v[1] + b0.y, 0.f);
        o[2] = fmaxf(0.25f * v[2] + b0.z, 0.f);
        o[3] = fmaxf(0.25f * v[3] + b0.w, 0.f);
        o[4] = fmaxf(0.25f * v[4] + b1.x, 0.f);
        o[5] = fmaxf(0.25f * v[5] + b1.y, 0.f);
        o[6] = fmaxf(0.25f * v[6] + b1.z, 0.f);
        o[7] = fmaxf(0.25f * v[7] + b1.w, 0.f);
        if (writeOut) {
            ((float4*)(dout + n * DD))[lane * 2]     = make_float4(o[0], o[1], o[2], o[3]);
            ((float4*)(dout + n * DD))[lane * 2 + 1] = make_float4(o[4], o[5], o[6], o[7]);
        } else {
            __half2 h0 = __floats2half2_rn(o[0], o[1]);
            __half2 h1 = __floats2half2_rn(o[2], o[3]);
            __half2 h2 = __floats2half2_rn(o[4], o[5]);
            __half2 h3 = __floats2half2_rn(o[6], o[7]);
            uint4 u;
            u.x = *(unsigned int*)&h0; u.y = *(unsigned int*)&h1;
            u.z = *(unsigned int*)&h2; u.w = *(unsigned int*)&h3;
            ((uint4*)(g_hh + (size_t)n * DD))[lane] = u;
        }
    }
}

// ---------------- launch ----------------
extern "C" void kernel_launch(void* const* d_in, const int* in_sizes, int n_in,
                              void* d_out, int out_size) {
    const float* x   = (const float*)d_in[0];
    const float* ea  = (const float*)d_in[1];
    const int*   ei  = (const int*)  d_in[2];
    const float* fW  = (const float*)d_in[3];
    const float* fb  = (const float*)d_in[4];
    const float* feW = (const float*)d_in[5];
    const float* feb = (const float*)d_in[6];
    const float* Wl  = (const float*)d_in[7];
    const float* bl  = (const float*)d_in[8];
    const float* Wr  = (const float*)d_in[9];
    const float* br  = (const float*)d_in[10];
    const float* We  = (const float*)d_in[11];
    const float* att = (const float*)d_in[12];
    const float* bias= (const float*)d_in[13];

    // prologue
    k_h0<<<(NN + 15) / 16, 256>>>(x, fW, fb);                 // also zeroes cnt/cur
    k_cvt<<<(512 * 64 + 256 * 32 + 255) / 256, 256>>>(Wl, Wr, We);
    k_hist<<<(NE + 255) / 256, 256>>>(ei);
    k_scan_a<<<NSB, 256>>>();
    k_scan_b<<<1, 256>>>();
    k_scan_c<<<NSB, 256>>>();
    k_scatter<<<(NE + 255) / 256, 256>>>(ei);
    k_ee_tc<<<dim3(NE / 128, 4), 256>>>(ea, feW, feb);

    for (int l = 0; l < 3; l++) {
        k_lin_tc<<<dim3((NN + 127) / 128, 8), 256>>>(bl, br);
        k_fused<<<(NN + 7) / 8, 256>>>(att, bias, (float*)d_out, l == 2 ? 1 : 0);
    }
}